// round 6
// baseline (speedup 1.0000x reference)
#include <cuda_runtime.h>

#define EPSF 1e-5f

// ---------------- scratch (device globals; no allocation allowed) -------------
// B=4, C=2048, R=512, H=W=64, N=4096
__device__ float g_f   [4L*512*4096];     // 32 MB
__device__ float g_q   [4L*512*4096];
__device__ float g_kk  [4L*512*4096];
__device__ float g_v   [4L*512*4096];
__device__ float g_upd [4L*512*4096];
__device__ float g_attn[4L*4096*4096];    // 268 MB

// ---------------- generic tiled SGEMM -----------------------------------------
// C[m][n] = sum_k A(m,k) * B(k,n)   (+ optional B2 fused add, + optional BN+ReLU)
// AMODE 0: A stored [m][k], k contiguous (lda = row stride)
// AMODE 1: A stored [k][m], m contiguous
// BMODE 1: B stored [k][n], n contiguous
// BMODE 0: B stored [n][k], k contiguous
// EPI   1: out = relu(acc*inv[m] + (b - m*inv)[m]);  EPI 0: raw store
#define BM 128
#define BN 128
#define BKk 16

template<int AMODE, int BMODE, int EPI, int HASB2>
__global__ __launch_bounds__(256, 2)
void gemm_k(const float* __restrict__ A,  long sA, int lda,
            const float* __restrict__ Bp, long sB, int ldb,
            const float* __restrict__ B2, long sB2,
            float* __restrict__ Cp, long sC, int ldc,
            const float* __restrict__ vg, const float* __restrict__ vb,
            const float* __restrict__ vm, const float* __restrict__ vv,
            int K)
{
    const int bz = blockIdx.z;
    A  += (long)bz * sA;
    Bp += (long)bz * sB;
    Cp += (long)bz * sC;
    if (HASB2) B2 += (long)bz * sB2;

    const int m0 = blockIdx.y * BM;
    const int n0 = blockIdx.x * BN;

    __shared__ float As[BKk][BM];
    __shared__ float Bs[BKk][BN];

    const int tid = threadIdx.x;
    const int tx = tid & 15;          // 0..15
    const int ty = tid >> 4;          // 0..15

    float acc[8][8];
    #pragma unroll
    for (int i = 0; i < 8; i++)
        #pragma unroll
        for (int j = 0; j < 8; j++) acc[i][j] = 0.f;

    for (int k0 = 0; k0 < K; k0 += BKk) {
        // ---- load A tile ----
        if (AMODE == 0) {
            int r = tid >> 2;             // 0..63
            int c = (tid & 3) * 4;        // 0,4,8,12
            #pragma unroll
            for (int it = 0; it < 2; it++) {
                int m = r + it * 64;
                float4 a = *(const float4*)&A[(long)(m0 + m) * lda + k0 + c];
                As[c + 0][m] = a.x; As[c + 1][m] = a.y;
                As[c + 2][m] = a.z; As[c + 3][m] = a.w;
            }
        } else {
            int kk = tid >> 5;            // 0..7
            int mi = (tid & 31) * 4;      // 0..124
            #pragma unroll
            for (int it = 0; it < 2; it++) {
                int k = kk + it * 8;
                *(float4*)&As[k][mi] =
                    *(const float4*)&A[(long)(k0 + k) * lda + m0 + mi];
            }
        }
        // ---- load B tile ----
        if (BMODE == 1) {
            int kk = tid >> 5;
            int ni = (tid & 31) * 4;
            #pragma unroll
            for (int it = 0; it < 2; it++) {
                int k = kk + it * 8;
                float4 v4 = *(const float4*)&Bp[(long)(k0 + k) * ldb + n0 + ni];
                if (HASB2) {
                    float4 w4 = *(const float4*)&B2[(long)(k0 + k) * ldb + n0 + ni];
                    v4.x += w4.x; v4.y += w4.y; v4.z += w4.z; v4.w += w4.w;
                }
                *(float4*)&Bs[k][ni] = v4;
            }
        } else {
            int r = tid >> 2;
            int c = (tid & 3) * 4;
            #pragma unroll
            for (int it = 0; it < 2; it++) {
                int n = r + it * 64;
                float4 v4 = *(const float4*)&Bp[(long)(n0 + n) * ldb + k0 + c];
                Bs[c + 0][n] = v4.x; Bs[c + 1][n] = v4.y;
                Bs[c + 2][n] = v4.z; Bs[c + 3][n] = v4.w;
            }
        }
        __syncthreads();

        // ---- compute ----
        #pragma unroll
        for (int k = 0; k < BKk; k++) {
            float a[8], b[8];
            float4 a0 = *(const float4*)&As[k][ty * 8];
            float4 a1 = *(const float4*)&As[k][ty * 8 + 4];
            float4 b0 = *(const float4*)&Bs[k][tx * 8];
            float4 b1 = *(const float4*)&Bs[k][tx * 8 + 4];
            a[0]=a0.x; a[1]=a0.y; a[2]=a0.z; a[3]=a0.w;
            a[4]=a1.x; a[5]=a1.y; a[6]=a1.z; a[7]=a1.w;
            b[0]=b0.x; b[1]=b0.y; b[2]=b0.z; b[3]=b0.w;
            b[4]=b1.x; b[5]=b1.y; b[6]=b1.z; b[7]=b1.w;
            #pragma unroll
            for (int i = 0; i < 8; i++)
                #pragma unroll
                for (int j = 0; j < 8; j++)
                    acc[i][j] = fmaf(a[i], b[j], acc[i][j]);
        }
        __syncthreads();
    }

    // ---- epilogue ----
    #pragma unroll
    for (int i = 0; i < 8; i++) {
        const int row = m0 + ty * 8 + i;
        float inv = 0.f, bet = 0.f;
        if (EPI == 1) {
            inv = vg[row] * rsqrtf(vv[row] + EPSF);
            bet = vb[row] - vm[row] * inv;
        }
        float4 o0, o1;
        if (EPI == 1) {
            o0.x = fmaxf(fmaf(acc[i][0], inv, bet), 0.f);
            o0.y = fmaxf(fmaf(acc[i][1], inv, bet), 0.f);
            o0.z = fmaxf(fmaf(acc[i][2], inv, bet), 0.f);
            o0.w = fmaxf(fmaf(acc[i][3], inv, bet), 0.f);
            o1.x = fmaxf(fmaf(acc[i][4], inv, bet), 0.f);
            o1.y = fmaxf(fmaf(acc[i][5], inv, bet), 0.f);
            o1.z = fmaxf(fmaf(acc[i][6], inv, bet), 0.f);
            o1.w = fmaxf(fmaf(acc[i][7], inv, bet), 0.f);
        } else {
            o0.x = acc[i][0]; o0.y = acc[i][1]; o0.z = acc[i][2]; o0.w = acc[i][3];
            o1.x = acc[i][4]; o1.y = acc[i][5]; o1.z = acc[i][6]; o1.w = acc[i][7];
        }
        float* cp = &Cp[(long)row * ldc + n0 + tx * 8];
        *(float4*)cp       = o0;
        *(float4*)(cp + 4) = o1;
    }
}

// ---------------- row softmax (rows of 4096) ----------------------------------
__global__ void softmax_k(float* __restrict__ S)
{
    const long row = blockIdx.x;
    float4* p = (float4*)(S + row * 4096);
    const int tid = threadIdx.x;   // 256 threads, 16 elements each

    float4 v[4];
    float mx = -3.4e38f;
    #pragma unroll
    for (int i = 0; i < 4; i++) {
        v[i] = p[tid + 256 * i];
        mx = fmaxf(mx, fmaxf(fmaxf(v[i].x, v[i].y), fmaxf(v[i].z, v[i].w)));
    }

    __shared__ float red[256];
    red[tid] = mx; __syncthreads();
    #pragma unroll
    for (int s = 128; s > 0; s >>= 1) {
        if (tid < s) red[tid] = fmaxf(red[tid], red[tid + s]);
        __syncthreads();
    }
    mx = red[0];
    __syncthreads();

    float sum = 0.f;
    #pragma unroll
    for (int i = 0; i < 4; i++) {
        v[i].x = __expf(v[i].x - mx); v[i].y = __expf(v[i].y - mx);
        v[i].z = __expf(v[i].z - mx); v[i].w = __expf(v[i].w - mx);
        sum += v[i].x + v[i].y + v[i].z + v[i].w;
    }
    red[tid] = sum; __syncthreads();
    #pragma unroll
    for (int s = 128; s > 0; s >>= 1) {
        if (tid < s) red[tid] += red[tid + s];
        __syncthreads();
    }
    const float r = 1.f / red[0];
    #pragma unroll
    for (int i = 0; i < 4; i++) {
        v[i].x *= r; v[i].y *= r; v[i].z *= r; v[i].w *= r;
        p[tid + 256 * i] = v[i];
    }
}

// ---------------- launch --------------------------------------------------------
extern "C" void kernel_launch(void* const* d_in, const int* in_sizes, int n_in,
                              void* d_out, int out_size)
{
    const float* feature = (const float*)d_in[0];
    const float* rW = (const float*)d_in[1];
    const float* rg = (const float*)d_in[2];
    const float* rb = (const float*)d_in[3];
    const float* rm = (const float*)d_in[4];
    const float* rv = (const float*)d_in[5];
    const float* qW = (const float*)d_in[6];
    const float* qg = (const float*)d_in[7];
    const float* qb = (const float*)d_in[8];
    const float* qm = (const float*)d_in[9];
    const float* qv = (const float*)d_in[10];
    const float* kW = (const float*)d_in[11];
    const float* kg = (const float*)d_in[12];
    const float* kb = (const float*)d_in[13];
    const float* km = (const float*)d_in[14];
    const float* kv = (const float*)d_in[15];
    const float* vW = (const float*)d_in[16];
    const float* vg = (const float*)d_in[17];
    const float* vb = (const float*)d_in[18];
    const float* vm = (const float*)d_in[19];
    const float* vvp = (const float*)d_in[20];
    const float* uW = (const float*)d_in[21];
    const float* ug = (const float*)d_in[22];
    const float* ub = (const float*)d_in[23];
    const float* um = (const float*)d_in[24];
    const float* uv = (const float*)d_in[25];

    float *f, *q, *k, *v, *attn, *upd;
    cudaGetSymbolAddress((void**)&f,    g_f);
    cudaGetSymbolAddress((void**)&q,    g_q);
    cudaGetSymbolAddress((void**)&k,    g_kk);
    cudaGetSymbolAddress((void**)&v,    g_v);
    cudaGetSymbolAddress((void**)&attn, g_attn);
    cudaGetSymbolAddress((void**)&upd,  g_upd);

    const long sF = 512L * 4096;          // per-batch stride of f/q/k/v/upd
    const long sX = 2048L * 4096;         // per-batch stride of feature / out
    const long sS = 4096L * 4096;         // per-batch stride of attn
    dim3 blk(256);

    // 1) f = relu(bn(rW @ feature))            M=512 N=4096 K=2048
    gemm_k<0,1,1,0><<<dim3(32,4,4), blk>>>(rW, 0, 2048,
                                           feature, sX, 4096,
                                           nullptr, 0,
                                           f, sF, 4096,
                                           rg, rb, rm, rv, 2048);
    // 2) q,k,v from f                          M=512 N=4096 K=512
    gemm_k<0,1,1,0><<<dim3(32,4,4), blk>>>(qW, 0, 512, f, sF, 4096, nullptr, 0,
                                           q, sF, 4096, qg, qb, qm, qv, 512);
    gemm_k<0,1,1,0><<<dim3(32,4,4), blk>>>(kW, 0, 512, f, sF, 4096, nullptr, 0,
                                           k, sF, 4096, kg, kb, km, kv, 512);
    gemm_k<0,1,1,0><<<dim3(32,4,4), blk>>>(vW, 0, 512, f, sF, 4096, nullptr, 0,
                                           v, sF, 4096, vg, vb, vm, vvp, 512);
    // 3) S[n][m] = sum_c q[c][n] k[c][m]       M=4096 N=4096 K=512
    gemm_k<1,1,0,0><<<dim3(32,32,4), blk>>>(q, sF, 4096,
                                            k, sF, 4096,
                                            nullptr, 0,
                                            attn, sS, 4096,
                                            nullptr, nullptr, nullptr, nullptr, 512);
    // 4) softmax rows
    softmax_k<<<4 * 4096, 256>>>(attn);
    // 5) upd[c][n] = sum_m v[c][m] attn[n][m]  M=512 N=4096 K=4096
    gemm_k<0,0,0,0><<<dim3(32,4,4), blk>>>(v, sF, 4096,
                                           attn, sS, 4096,
                                           nullptr, 0,
                                           upd, sF, 4096,
                                           nullptr, nullptr, nullptr, nullptr, 4096);
    // 6) out = relu(bn(uW @ (f + upd)))        M=2048 N=4096 K=512
    gemm_k<0,1,1,1><<<dim3(32,16,4), blk>>>(uW, 0, 512,
                                            f, sF, 4096,
                                            upd, sF,
                                            (float*)d_out, sX, 4096,
                                            ug, ub, um, uv, 512);
}